// round 10
// baseline (speedup 1.0000x reference)
#include <cuda_runtime.h>
#include <cuda_fp16.h>
#include <cstdint>

// NLM_7962869366897 — Round 10: m32n32 warp tiles for 3 CTAs/SM.
// R9 was latency-bound at 16 warps/SM (126 regs, occ 23.5%, issue 41%, no
// pipe >48%). Halving the warp tile (acc 64->32 regs, B-frags 32->16) drops
// to ~84 regs -> __launch_bounds__(256,3) -> 24 warps/SM. Groups of 64 rows,
// warps = (mt in {0,1}) x (nq in 0..3): value cols nq*16..+15, gates +64.

#define DEV_INLINE __device__ __forceinline__

constexpr int kD  = 2048;
constexpr int kM  = 32;
constexpr int kH2 = 128;
constexpr int kH  = 64;

__device__ __half g_wt[(size_t)kD * kH2 * kM];   // [d][h][m], fp16

DEV_INLINE float fast_sigmoid(float x) {
    float t; asm("tanh.approx.f32 %0, %1;" : "=f"(t) : "f"(0.5f * x));
    return fmaf(0.5f, t, 0.5f);
}
DEV_INLINE uint32_t smem_u32(const void* p) {
    uint32_t a;
    asm("{ .reg .u64 t; cvta.to.shared.u64 t, %1; cvt.u32.u64 %0, t; }" : "=r"(a) : "l"(p));
    return a;
}
DEV_INLINE void ldsm_x4(uint32_t* r, uint32_t addr) {
    asm volatile("ldmatrix.sync.aligned.m8n8.x4.shared.b16 {%0,%1,%2,%3}, [%4];"
                 : "=r"(r[0]), "=r"(r[1]), "=r"(r[2]), "=r"(r[3]) : "r"(addr));
}
DEV_INLINE void mma_f16(float* c, const uint32_t* a, const uint32_t* b) {
    asm volatile(
        "mma.sync.aligned.m16n8k16.row.col.f32.f16.f16.f32 "
        "{%0,%1,%2,%3}, {%4,%5,%6,%7}, {%8,%9}, {%0,%1,%2,%3};"
        : "+f"(c[0]), "+f"(c[1]), "+f"(c[2]), "+f"(c[3])
        : "r"(a[0]), "r"(a[1]), "r"(a[2]), "r"(a[3]), "r"(b[0]), "r"(b[1]));
}
DEV_INLINE void cp_async16(uint32_t dst, const void* src) {
    asm volatile("cp.async.cg.shared.global [%0], [%1], 16;"
                 :: "r"(dst), "l"(__cvta_generic_to_global(src)) : "memory");
}
#define CP_COMMIT() asm volatile("cp.async.commit_group;" ::: "memory")
#define CP_WAIT0()  asm volatile("cp.async.wait_group 0;" ::: "memory")

DEV_INLINE void sts_half8(char* dst, float4 v) {
    __half2 h0 = __floats2half2_rn(v.x, v.y);
    __half2 h1 = __floats2half2_rn(v.z, v.w);
    uint2 u;
    u.x = *reinterpret_cast<uint32_t*>(&h0);
    u.y = *reinterpret_cast<uint32_t*>(&h1);
    *reinterpret_cast<uint2*>(dst) = u;
}

// ---------------- prepass: transpose + fp16 convert ----------------
__global__ __launch_bounds__(256)
void transpose_kernel(const float* __restrict__ w1a) {
    __shared__ float tile[32][33];
    const int h  = blockIdx.y;
    const int d0 = blockIdx.x * 32;
    const int lane = threadIdx.x & 31;
    const int w    = threadIdx.x >> 5;
    #pragma unroll
    for (int m = w; m < 32; m += 8)
        tile[m][lane] = w1a[((size_t)(m * kH2 + h)) * kD + d0 + lane];
    __syncthreads();
    #pragma unroll
    for (int dl = w; dl < 32; dl += 8)
        g_wt[((size_t)(d0 + dl) * kH2 + h) * kM + lane] =
            __float2half_rn(tile[lane][dl]);
}

// ---------------- main kernel ----------------
constexpr int PITCH_B   = 80;                 // bytes per fp16 row
constexpr int ABYTES_H  = 64 * PITCH_B;       // 5120 (64-row group)
constexpr int OFF_BH    = 2 * ABYTES_H;       // 10240
constexpr int OFF_PS    = OFF_BH + 128 * PITCH_B;  // 20480 (ps: 64*8 floats)
constexpr int OFF_W2    = OFF_PS + 2048;      // 22528
constexpr int OFF_BI1   = OFF_W2 + 512;       // 23040
constexpr int OFF_BI2   = OFF_BI1 + 512;      // 23552
constexpr int SMEM_BYTES = OFF_BI2 + 32;      // 23584

__global__ __launch_bounds__(256, 3)
void nlm_mma_kernel(const float* __restrict__ state,   // [B, D, M]
                    const float* __restrict__ b1a,     // [1, D, 2H]
                    const float* __restrict__ Ta,
                    const float* __restrict__ w1b,     // [H, 2, D]
                    const float* __restrict__ b1b,     // [1, D, 2]
                    const float* __restrict__ Tb,
                    float* __restrict__ out) {         // [B, D]
    extern __shared__ __align__(16) char sm[];
    char*   Ah   = sm;
    char*   Bh   = sm + OFF_BH;
    float*  ps   = reinterpret_cast<float*>(sm + OFF_PS);
    float2* sW2  = reinterpret_cast<float2*>(sm + OFF_W2);
    float*  sBi1 = reinterpret_cast<float*>(sm + OFF_BI1);
    float*  sBi2 = reinterpret_cast<float*>(sm + OFF_BI2);

    const int d    = blockIdx.x;
    const int tid  = threadIdx.x;
    const int lane = tid & 31;
    const int wid  = tid >> 5;
    const int mt   = wid & 1;      // m-tile: rows mt*32..+31 of 64-row group
    const int nq   = wid >> 1;     // n-quarter: value cols nq*16..+15, gates +64

    const uint32_t sAh = smem_u32(Ah);
    const uint32_t sBh = smem_u32(Bh);

    // A staging roles: 32 rows per 256-thread pass, 4-wf coalesced
    const int arow = tid >> 3;
    const int ac   = tid & 7;

    // ---- stage B (weights, fp16) via cp.async ----
    {
        const char* wsrc = reinterpret_cast<const char*>(g_wt + (size_t)d * kH2 * kM);
        #pragma unroll
        for (int t = 0; t < 2; t++) {
            const int c = tid + t * 256;
            const int h = c >> 2, cc = c & 3;
            cp_async16(sBh + (uint32_t)(h * PITCH_B + cc * 16), wsrc + h * 64 + cc * 16);
        }
        CP_COMMIT();
    }
    // ---- stage A(0): rows 0..63 ----
    #pragma unroll
    for (int t = 0; t < 2; t++) {
        const int row = arow + t * 32;
        const float4 v = __ldg(reinterpret_cast<const float4*>(
            state + ((size_t)row * kD + d) * kM) + ac);
        sts_half8(Ah + row * PITCH_B + ac * 8, v);
    }
    if (tid < kH)
        sW2[tid] = make_float2(__ldg(w1b + (size_t)(tid * 2 + 0) * kD + d),
                               __ldg(w1b + (size_t)(tid * 2 + 1) * kD + d));
    if (tid < kH2) sBi1[tid] = b1a[(size_t)d * kH2 + tid];
    if (tid < 2)   sBi2[tid] = b1b[(size_t)d * 2 + tid];
    const float rTa = 1.0f / __ldg(Ta);
    const float rTb = 1.0f / __ldg(Tb);

    // ---- ldmatrix addresses ----
    const uint32_t aBase = sAh +
        (uint32_t)((mt * 32 + ((lane >> 3) & 1) * 8 + (lane & 7)) * PITCH_B +
                   (lane >> 4) * 16);
    const uint32_t bBase = sBh +
        (uint32_t)((nq * 16 + ((lane >> 4) & 1) * 8 + (lane & 7)) * PITCH_B +
                   ((lane >> 3) & 1) * 16);
    const uint32_t bGate = bBase + 64u * PITCH_B;
    const int hq = (lane & 3) * 2;

    CP_WAIT0();
    __syncthreads();

    // ---- hoisted per-thread constants: biases (8 regs) ----
    const float2 bv0 = *reinterpret_cast<const float2*>(&sBi1[nq * 16 + hq]);
    const float2 bv8 = *reinterpret_cast<const float2*>(&sBi1[nq * 16 + 8 + hq]);
    const float2 bg0 = *reinterpret_cast<const float2*>(&sBi1[64 + nq * 16 + hq]);
    const float2 bg8 = *reinterpret_cast<const float2*>(&sBi1[64 + nq * 16 + 8 + hq]);

    // ---- B fragments: load ONCE (16 regs) ----
    uint32_t fbv[2][4], fbg[2][4];
    #pragma unroll
    for (int k = 0; k < 2; k++) {
        ldsm_x4(fbv[k], bBase + k * 32);   // value n8 tiles (cols +0-7, +8-15)
        ldsm_x4(fbg[k], bGate + k * 32);   // gate  n8 tiles
    }

    for (int g = 0; g < 8; g++) {
        // ---- prefetch A(g+1): 2 LDG.128/thread ----
        float4 pf0, pf1;
        if (g < 7) {
            const int b0n = (g + 1) * 64;
            pf0 = __ldg(reinterpret_cast<const float4*>(
                state + ((size_t)(b0n + arow) * kD + d) * kM) + ac);
            pf1 = __ldg(reinterpret_cast<const float4*>(
                state + ((size_t)(b0n + arow + 32) * kD + d) * kM) + ac);
        }
        // ---- finalize previous group's output ----
        if (g > 0 && tid < 64) {
            const float4 q0 = *reinterpret_cast<const float4*>(&ps[tid * 8]);
            const float4 q1 = *reinterpret_cast<const float4*>(&ps[tid * 8 + 4]);
            const float p0 = q0.x + q0.z + q1.x + q1.z;
            const float p1 = q0.y + q0.w + q1.y + q1.w;
            const float u0 = (p0 + sBi2[0]) * rTb;
            const float u1 = (p1 + sBi2[1]) * rTb;
            out[(size_t)((g - 1) * 64 + tid) * kD + d] = u0 * fast_sigmoid(u1);
        }

        // ---- init accumulators with hoisted biases (32 regs) ----
        float acc[2][4][4];   // [m-frag][v0,v1,g0,g1][c0..c3]
        #pragma unroll
        for (int f = 0; f < 2; f++) {
            acc[f][0][0] = bv0.x; acc[f][0][1] = bv0.y;
            acc[f][0][2] = bv0.x; acc[f][0][3] = bv0.y;
            acc[f][1][0] = bv8.x; acc[f][1][1] = bv8.y;
            acc[f][1][2] = bv8.x; acc[f][1][3] = bv8.y;
            acc[f][2][0] = bg0.x; acc[f][2][1] = bg0.y;
            acc[f][2][2] = bg0.x; acc[f][2][3] = bg0.y;
            acc[f][3][0] = bg8.x; acc[f][3][1] = bg8.y;
            acc[f][3][2] = bg8.x; acc[f][3][3] = bg8.y;
        }

        // ---- mainloop: 2 k16-steps, 8 MMA each ----
        const uint32_t aA = aBase + (uint32_t)((g & 1) * ABYTES_H);
        #pragma unroll
        for (int k = 0; k < 2; k++) {
            uint32_t a0[4], a1[4];
            ldsm_x4(a0, aA + k * 32);                   // rows +0..15
            ldsm_x4(a1, aA + 16 * PITCH_B + k * 32);    // rows +16..31
            mma_f16(acc[0][0], a0, fbv[k] + 0); mma_f16(acc[0][1], a0, fbv[k] + 2);
            mma_f16(acc[0][2], a0, fbg[k] + 0); mma_f16(acc[0][3], a0, fbg[k] + 2);
            mma_f16(acc[1][0], a1, fbv[k] + 0); mma_f16(acc[1][1], a1, fbv[k] + 2);
            mma_f16(acc[1][2], a1, fbg[k] + 0); mma_f16(acc[1][3], a1, fbg[k] + 2);
        }

        // ---- GLU1 + layer-2 partials, 2-shfl reduce -> ps ----
        const float4 w2a = *reinterpret_cast<const float4*>(&sW2[nq * 16 + hq]);
        const float4 w2b = *reinterpret_cast<const float4*>(&sW2[nq * 16 + 8 + hq]);

        #pragma unroll
        for (int f = 0; f < 2; f++) {
            #pragma unroll
            for (int rh = 0; rh < 2; rh++) {
                const float x0 = (acc[f][0][rh * 2 + 0] * rTa) *
                                 fast_sigmoid(acc[f][2][rh * 2 + 0] * rTa);
                const float x1 = (acc[f][0][rh * 2 + 1] * rTa) *
                                 fast_sigmoid(acc[f][2][rh * 2 + 1] * rTa);
                const float x2 = (acc[f][1][rh * 2 + 0] * rTa) *
                                 fast_sigmoid(acc[f][3][rh * 2 + 0] * rTa);
                const float x3 = (acc[f][1][rh * 2 + 1] * rTa) *
                                 fast_sigmoid(acc[f][3][rh * 2 + 1] * rTa);
                float p0 = x0 * w2a.x + x1 * w2a.z + x2 * w2b.x + x3 * w2b.z;
                float p1 = x0 * w2a.y + x1 * w2a.w + x2 * w2b.y + x3 * w2b.w;
                p0 += __shfl_xor_sync(0xffffffffu, p0, 1);
                p0 += __shfl_xor_sync(0xffffffffu, p0, 2);
                p1 += __shfl_xor_sync(0xffffffffu, p1, 1);
                p1 += __shfl_xor_sync(0xffffffffu, p1, 2);
                if ((lane & 3) == 0) {
                    const int row = mt * 32 + f * 16 + rh * 8 + (lane >> 2);
                    *reinterpret_cast<float2*>(&ps[row * 8 + nq * 2]) =
                        make_float2(p0, p1);
                }
            }
        }

        // ---- store prefetched A(g+1) ----
        if (g < 7) {
            char* nbuf = Ah + ((g + 1) & 1) * ABYTES_H;
            sts_half8(nbuf + arow * PITCH_B + ac * 8, pf0);
            sts_half8(nbuf + (arow + 32) * PITCH_B + ac * 8, pf1);
        }
        __syncthreads();
    }

    // ---- finalize last group ----
    if (tid < 64) {
        const float4 q0 = *reinterpret_cast<const float4*>(&ps[tid * 8]);
        const float4 q1 = *reinterpret_cast<const float4*>(&ps[tid * 8 + 4]);
        const float p0 = q0.x + q0.z + q1.x + q1.z;
        const float p1 = q0.y + q0.w + q1.y + q1.w;
        const float u0 = (p0 + sBi2[0]) * rTb;
        const float u1 = (p1 + sBi2[1]) * rTb;
        out[(size_t)(7 * 64 + tid) * kD + d] = u0 * fast_sigmoid(u1);
    }
}

// ---------------- launch ----------------
extern "C" void kernel_launch(void* const* d_in, const int* in_sizes, int n_in,
                              void* d_out, int out_size) {
    const float* state = (const float*)d_in[0];
    const float* w1a   = (const float*)d_in[1];
    const float* b1a   = (const float*)d_in[2];
    const float* Ta    = (const float*)d_in[3];
    const float* w1b   = (const float*)d_in[4];
    const float* b1b   = (const float*)d_in[5];
    const float* Tb    = (const float*)d_in[6];
    float* out = (float*)d_out;

    cudaFuncSetAttribute(nlm_mma_kernel,
                         cudaFuncAttributeMaxDynamicSharedMemorySize, SMEM_BYTES);

    transpose_kernel<<<dim3(kD / 32, kH2), 256>>>(w1a);
    nlm_mma_kernel<<<kD, 256, SMEM_BYTES>>>(state, b1a, Ta, w1b, b1b, Tb, out);
}

// round 11
// speedup vs baseline: 1.0124x; 1.0124x over previous
#include <cuda_runtime.h>
#include <cuda_fp16.h>
#include <cstdint>

// NLM_7962869366897 — Round 11: R9 structure + fp16 accumulators.
// R10 proved tile-shrink trades L1 for occupancy at a net loss; R9's m32n64
// decomposition is L1-minimal. The register cut with ZERO L1 cost is fp16
// MMA accumulation (C/D = 2 regs per n8 tile): acc 64 -> 32 regs, ~84 total
// -> __launch_bounds__(256,3) -> 24 warps/SM. Everything downstream of the
// MMA stays fp32 (GLU, layer 2, output).

#define DEV_INLINE __device__ __forceinline__

constexpr int kD  = 2048;
constexpr int kM  = 32;
constexpr int kH2 = 128;
constexpr int kH  = 64;

__device__ __half g_wt[(size_t)kD * kH2 * kM];   // [d][h][m], fp16

DEV_INLINE float fast_sigmoid(float x) {
    float t; asm("tanh.approx.f32 %0, %1;" : "=f"(t) : "f"(0.5f * x));
    return fmaf(0.5f, t, 0.5f);
}
DEV_INLINE uint32_t smem_u32(const void* p) {
    uint32_t a;
    asm("{ .reg .u64 t; cvta.to.shared.u64 t, %1; cvt.u32.u64 %0, t; }" : "=r"(a) : "l"(p));
    return a;
}
DEV_INLINE void ldsm_x4(uint32_t* r, uint32_t addr) {
    asm volatile("ldmatrix.sync.aligned.m8n8.x4.shared.b16 {%0,%1,%2,%3}, [%4];"
                 : "=r"(r[0]), "=r"(r[1]), "=r"(r[2]), "=r"(r[3]) : "r"(addr));
}
// fp16-accumulate MMA: C/D = 2 regs (half2 x2): reg0 = rows g, reg1 = rows g+8,
// each packing cols (2c, 2c+1) — same positions as the fp32 layout, packed.
DEV_INLINE void mma_f16acc(uint32_t* c, const uint32_t* a, const uint32_t* b) {
    asm volatile(
        "mma.sync.aligned.m16n8k16.row.col.f16.f16.f16.f16 "
        "{%0,%1}, {%2,%3,%4,%5}, {%6,%7}, {%0,%1};"
        : "+r"(c[0]), "+r"(c[1])
        : "r"(a[0]), "r"(a[1]), "r"(a[2]), "r"(a[3]), "r"(b[0]), "r"(b[1]));
}
DEV_INLINE void cp_async16(uint32_t dst, const void* src) {
    asm volatile("cp.async.cg.shared.global [%0], [%1], 16;"
                 :: "r"(dst), "l"(__cvta_generic_to_global(src)) : "memory");
}
#define CP_COMMIT() asm volatile("cp.async.commit_group;" ::: "memory")
#define CP_WAIT0()  asm volatile("cp.async.wait_group 0;" ::: "memory")

DEV_INLINE void sts_half8(char* dst, float4 v) {
    __half2 h0 = __floats2half2_rn(v.x, v.y);
    __half2 h1 = __floats2half2_rn(v.z, v.w);
    uint2 u;
    u.x = *reinterpret_cast<uint32_t*>(&h0);
    u.y = *reinterpret_cast<uint32_t*>(&h1);
    *reinterpret_cast<uint2*>(dst) = u;
}

// ---------------- prepass: transpose + fp16 convert ----------------
__global__ __launch_bounds__(256)
void transpose_kernel(const float* __restrict__ w1a) {
    __shared__ float tile[32][33];
    const int h  = blockIdx.y;
    const int d0 = blockIdx.x * 32;
    const int lane = threadIdx.x & 31;
    const int w    = threadIdx.x >> 5;
    #pragma unroll
    for (int m = w; m < 32; m += 8)
        tile[m][lane] = w1a[((size_t)(m * kH2 + h)) * kD + d0 + lane];
    __syncthreads();
    #pragma unroll
    for (int dl = w; dl < 32; dl += 8)
        g_wt[((size_t)(d0 + dl) * kH2 + h) * kM + lane] =
            __float2half_rn(tile[lane][dl]);
}

// ---------------- main kernel ----------------
constexpr int PITCH_B   = 80;                 // bytes per fp16 row (ldsm-safe)
constexpr int ABYTES_H  = 128 * PITCH_B;      // 10240
constexpr int OFF_BH    = 2 * ABYTES_H;       // 20480
constexpr int OFF_PS    = OFF_BH + ABYTES_H;  // 30720 (ps: 128*4 floats)
constexpr int OFF_W2    = OFF_PS + 2048;      // float2[64]
constexpr int OFF_BI1H  = OFF_W2 + 512;       // half2-packed biases, 64 u32
constexpr int OFF_BI2   = OFF_BI1H + 256;
constexpr int SMEM_BYTES = OFF_BI2 + 32;

__global__ __launch_bounds__(256, 3)
void nlm_mma_kernel(const float* __restrict__ state,   // [B, D, M]
                    const float* __restrict__ b1a,     // [1, D, 2H]
                    const float* __restrict__ Ta,
                    const float* __restrict__ w1b,     // [H, 2, D]
                    const float* __restrict__ b1b,     // [1, D, 2]
                    const float* __restrict__ Tb,
                    float* __restrict__ out) {         // [B, D]
    extern __shared__ __align__(16) char sm[];
    char*     Ah    = sm;
    char*     Bh    = sm + OFF_BH;
    float*    ps    = reinterpret_cast<float*>(sm + OFF_PS);
    float2*   sW2   = reinterpret_cast<float2*>(sm + OFF_W2);
    uint32_t* sBi1h = reinterpret_cast<uint32_t*>(sm + OFF_BI1H);
    float*    sBi2  = reinterpret_cast<float*>(sm + OFF_BI2);

    const int d    = blockIdx.x;
    const int tid  = threadIdx.x;
    const int lane = tid & 31;
    const int wid  = tid >> 5;
    const int mt   = wid & 3;      // m-tile: rows mt*32..+31
    const int nh   = wid >> 2;     // n-half: value cols nh*32..+31, gates +64

    const uint32_t sAh = smem_u32(Ah);
    const uint32_t sBh = smem_u32(Bh);

    const int arow = tid >> 3;     // coalesced staging: 1 wf per 128B line
    const int ac   = tid & 7;

    // ---- stage B via cp.async (raw fp16 copy) ----
    {
        const char* wsrc = reinterpret_cast<const char*>(g_wt + (size_t)d * kH2 * kM);
        #pragma unroll
        for (int t = 0; t < 2; t++) {
            const int c = tid + t * 256;
            const int h = c >> 2, cc = c & 3;
            cp_async16(sBh + (uint32_t)(h * PITCH_B + cc * 16), wsrc + h * 64 + cc * 16);
        }
        CP_COMMIT();
    }
    // ---- stage A(0): coalesced LDG.128 -> cvt -> STS.64 ----
    #pragma unroll
    for (int t = 0; t < 4; t++) {
        const int row = arow + t * 32;
        const float4 v = __ldg(reinterpret_cast<const float4*>(
            state + ((size_t)row * kD + d) * kM) + ac);
        sts_half8(Ah + row * PITCH_B + ac * 8, v);
    }
    if (tid < kH)
        sW2[tid] = make_float2(__ldg(w1b + (size_t)(tid * 2 + 0) * kD + d),
                               __ldg(w1b + (size_t)(tid * 2 + 1) * kD + d));
    if (tid < kH)  {  // pack layer-1 bias pairs (h, h+1) to half2
        const float2 bp = *reinterpret_cast<const float2*>(
            b1a + (size_t)d * kH2 + tid * 2);
        __half2 h2 = __floats2half2_rn(bp.x, bp.y);
        sBi1h[tid] = *reinterpret_cast<uint32_t*>(&h2);
    }
    if (tid < 2)   sBi2[tid] = b1b[(size_t)d * 2 + tid];
    const float rTa = 1.0f / __ldg(Ta);
    const float rTb = 1.0f / __ldg(Tb);

    // ---- ldmatrix addresses ----
    const uint32_t aBase = sAh +
        (uint32_t)((mt * 32 + ((lane >> 3) & 1) * 8 + (lane & 7)) * PITCH_B +
                   (lane >> 4) * 16);
    const uint32_t bBase = sBh +
        (uint32_t)((nh * 32 + ((lane >> 4) & 1) * 8 + (lane & 7)) * PITCH_B +
                   ((lane >> 3) & 1) * 16);
    const int hq = (lane & 3) * 2;

    CP_WAIT0();
    __syncthreads();

    // ---- B fragments: load ONCE (32 regs) ----
    uint32_t fbv[2][4], fbg[2][4];
    #pragma unroll
    for (int k = 0; k < 2; k++) {
        ldsm_x4(fbv[k], bBase + k * 32);                    // value tiles 0,1
        ldsm_x4(fbg[k], bBase + 64 * PITCH_B + k * 32);     // gate tiles 0,1
    }
    uint32_t fbv2[2][4], fbg2[2][4];
    #pragma unroll
    for (int k = 0; k < 2; k++) {
        ldsm_x4(fbv2[k], bBase + 16 * PITCH_B + k * 32);    // value tiles 2,3
        ldsm_x4(fbg2[k], bBase + 80 * PITCH_B + k * 32);    // gate tiles 2,3
    }

    for (int g = 0; g < 4; g++) {
        // ---- prefetch A(g+1) phase 1 ----
        float4 pf0, pf1;
        if (g < 3) {
            const int b0n = (g + 1) * 128;
            pf0 = __ldg(reinterpret_cast<const float4*>(
                state + ((size_t)(b0n + arow) * kD + d) * kM) + ac);
            pf1 = __ldg(reinterpret_cast<const float4*>(
                state + ((size_t)(b0n + arow + 32) * kD + d) * kM) + ac);
        }
        // ---- finalize previous group's output ----
        if (g > 0 && tid < 128) {
            const float4 pp = *reinterpret_cast<const float4*>(&ps[tid * 4]);
            const float u0 = (pp.x + pp.z + sBi2[0]) * rTb;
            const float u1 = (pp.y + pp.w + sBi2[1]) * rTb;
            out[(size_t)((g - 1) * 128 + tid) * kD + d] = u0 * fast_sigmoid(u1);
        }

        // ---- init fp16 accumulators with biases (32 regs) ----
        uint32_t acc[2][8][2];   // [m-frag][q: 4 value + 4 gate][row-half]
        #pragma unroll
        for (int q = 0; q < 4; q++) {
            const uint32_t bv = sBi1h[nh * 16 + q * 4 + (lane & 3)];
            const uint32_t bg = sBi1h[32 + nh * 16 + q * 4 + (lane & 3)];
            #pragma unroll
            for (int f = 0; f < 2; f++) {
                acc[f][q][0] = bv;     acc[f][q][1] = bv;
                acc[f][q + 4][0] = bg; acc[f][q + 4][1] = bg;
            }
        }

        const uint32_t aA = aBase + (uint32_t)((g & 1) * ABYTES_H);
        char* nbuf = Ah + ((g + 1) & 1) * ABYTES_H;

        // ---- k = 0 ----
        {
            uint32_t a0[4], a1[4];
            ldsm_x4(a0, aA);
            ldsm_x4(a1, aA + 16 * PITCH_B);
            mma_f16acc(acc[0][0], a0, fbv[0] + 0); mma_f16acc(acc[0][1], a0, fbv[0] + 2);
            mma_f16acc(acc[0][2], a0, fbv2[0] + 0); mma_f16acc(acc[0][3], a0, fbv2[0] + 2);
            mma_f16acc(acc[0][4], a0, fbg[0] + 0); mma_f16acc(acc[0][5], a0, fbg[0] + 2);
            mma_f16acc(acc[0][6], a0, fbg2[0] + 0); mma_f16acc(acc[0][7], a0, fbg2[0] + 2);
            mma_f16acc(acc[1][0], a1, fbv[0] + 0); mma_f16acc(acc[1][1], a1, fbv[0] + 2);
            mma_f16acc(acc[1][2], a1, fbv2[0] + 0); mma_f16acc(acc[1][3], a1, fbv2[0] + 2);
            mma_f16acc(acc[1][4], a1, fbg[0] + 0); mma_f16acc(acc[1][5], a1, fbg[0] + 2);
            mma_f16acc(acc[1][6], a1, fbg2[0] + 0); mma_f16acc(acc[1][7], a1, fbg2[0] + 2);
        }
        // ---- store phase-1 prefetch, issue phase 2 ----
        if (g < 3) {
            sts_half8(nbuf + arow * PITCH_B + ac * 8, pf0);
            sts_half8(nbuf + (arow + 32) * PITCH_B + ac * 8, pf1);
            const int b0n = (g + 1) * 128;
            pf0 = __ldg(reinterpret_cast<const float4*>(
                state + ((size_t)(b0n + arow + 64) * kD + d) * kM) + ac);
            pf1 = __ldg(reinterpret_cast<const float4*>(
                state + ((size_t)(b0n + arow + 96) * kD + d) * kM) + ac);
        }
        // ---- k = 1 ----
        {
            uint32_t a0[4], a1[4];
            ldsm_x4(a0, aA + 32);
            ldsm_x4(a1, aA + 16 * PITCH_B + 32);
            mma_f16acc(acc[0][0], a0, fbv[1] + 0); mma_f16acc(acc[0][1], a0, fbv[1] + 2);
            mma_f16acc(acc[0][2], a0, fbv2[1] + 0); mma_f16acc(acc[0][3], a0, fbv2[1] + 2);
            mma_f16acc(acc[0][4], a0, fbg[1] + 0); mma_f16acc(acc[0][5], a0, fbg[1] + 2);
            mma_f16acc(acc[0][6], a0, fbg2[1] + 0); mma_f16acc(acc[0][7], a0, fbg2[1] + 2);
            mma_f16acc(acc[1][0], a1, fbv[1] + 0); mma_f16acc(acc[1][1], a1, fbv[1] + 2);
            mma_f16acc(acc[1][2], a1, fbv2[1] + 0); mma_f16acc(acc[1][3], a1, fbv2[1] + 2);
            mma_f16acc(acc[1][4], a1, fbg[1] + 0); mma_f16acc(acc[1][5], a1, fbg[1] + 2);
            mma_f16acc(acc[1][6], a1, fbg2[1] + 0); mma_f16acc(acc[1][7], a1, fbg2[1] + 2);
        }

        // ---- GLU1 + layer-2 partials (fp32), quad reduce -> ps ----
        float4 w2q[4];
        #pragma unroll
        for (int q = 0; q < 4; q++)
            w2q[q] = *reinterpret_cast<const float4*>(&sW2[nh * 32 + q * 8 + hq]);

        #pragma unroll
        for (int f = 0; f < 2; f++) {
            #pragma unroll
            for (int rh = 0; rh < 2; rh++) {
                float p0 = 0.0f, p1 = 0.0f;
                #pragma unroll
                for (int q = 0; q < 4; q++) {
                    const float2 vv = __half22float2(
                        *reinterpret_cast<__half2*>(&acc[f][q][rh]));
                    const float2 gg = __half22float2(
                        *reinterpret_cast<__half2*>(&acc[f][q + 4][rh]));
                    const float x0 = (vv.x * rTa) * fast_sigmoid(gg.x * rTa);
                    const float x1 = (vv.y * rTa) * fast_sigmoid(gg.y * rTa);
                    p0 = fmaf(x0, w2q[q].x, p0); p1 = fmaf(x0, w2q[q].y, p1);
                    p0 = fmaf(x1, w2q[q].z, p0); p1 = fmaf(x1, w2q[q].w, p1);
                }
                p0 += __shfl_xor_sync(0xffffffffu, p0, 1);
                p0 += __shfl_xor_sync(0xffffffffu, p0, 2);
                p1 += __shfl_xor_sync(0xffffffffu, p1, 1);
                p1 += __shfl_xor_sync(0xffffffffu, p1, 2);
                if ((lane & 3) == 0) {
                    const int row = mt * 32 + f * 16 + rh * 8 + (lane >> 2);
                    *reinterpret_cast<float2*>(&ps[row * 4 + nh * 2]) =
                        make_float2(p0, p1);
                }
            }
        }

        // ---- store phase-2 prefetch ----
        if (g < 3) {
            sts_half8(nbuf + (arow + 64) * PITCH_B + ac * 8, pf0);
            sts_half8(nbuf + (arow + 96) * PITCH_B + ac * 8, pf1);
        }
        __syncthreads();
    }

    // ---- finalize last group ----
    if (tid < 128) {
        const float4 pp = *reinterpret_cast<const float4*>(&ps[tid * 4]);
        const float u0 = (pp.x + pp.z + sBi2[0]) * rTb;
        const float u1 = (pp.y + pp.w + sBi2[1]) * rTb;
        out[(size_t)(3 * 128 + tid) * kD + d] = u0 * fast_sigmoid(u1);
    }
}

// ---------------- launch ----------------
extern "C" void kernel_launch(void* const* d_in, const int* in_sizes, int n_in,
                              void* d_out, int out_size) {
    const float* state = (const float*)d_in[0];
    const float* w1a   = (const float*)d_in[1];
    const float* b1a   = (const float*)d_in[2];
    const float* Ta    = (const float*)d_in[3];
    const float* w1b   = (const float*)d_in[4];
    const float* b1b   = (const float*)d_in[5];
    const float* Tb    = (const float*)d_in[6];
    float* out = (float*)d_out;

    cudaFuncSetAttribute(nlm_mma_kernel,
                         cudaFuncAttributeMaxDynamicSharedMemorySize, SMEM_BYTES);

    transpose_kernel<<<dim3(kD / 32, kH2), 256>>>(w1a);
    nlm_mma_kernel<<<kD, 256, SMEM_BYTES>>>(state, b1a, Ta, w1b, b1b, Tb, out);
}

// round 12
// speedup vs baseline: 1.0550x; 1.0421x over previous
#include <cuda_runtime.h>
#include <cuda_fp16.h>
#include <cstdint>

// NLM_7962869366897 — Round 12: R9 mainloop (proven optimum: m32n64, fp32 acc,
// 2 CTAs/SM) + three peripheral fixes:
//  1) outputs go to g_outT[d][b] coalesced (was: 8KB-strided STG = 512 wf/CTA
//     + 8x sector-amplified DRAM writes); tiny transpose kernel finalizes.
//  2) prepass rewritten at its DRAM floor (float4 reads, half2 writes).
//  3) 1/Ta folded into prepass weights + bias load; epilogue drops 64 FMULs.
// R10/R11 lesson: register cuts below 126 spill and cost more than occupancy pays.

#define DEV_INLINE __device__ __forceinline__

constexpr int kD  = 2048;
constexpr int kM  = 32;
constexpr int kH2 = 128;
constexpr int kH  = 64;
constexpr int kB  = 512;

__device__ __half g_wt[(size_t)kD * kH2 * kM];   // [d][h][m], fp16, pre-scaled by 1/Ta
__device__ float  g_outT[(size_t)kD * kB];       // [d][b] transposed output

DEV_INLINE float fast_sigmoid(float x) {
    float t; asm("tanh.approx.f32 %0, %1;" : "=f"(t) : "f"(0.5f * x));
    return fmaf(0.5f, t, 0.5f);
}
DEV_INLINE uint32_t smem_u32(const void* p) {
    uint32_t a;
    asm("{ .reg .u64 t; cvta.to.shared.u64 t, %1; cvt.u32.u64 %0, t; }" : "=r"(a) : "l"(p));
    return a;
}
DEV_INLINE void ldsm_x4(uint32_t* r, uint32_t addr) {
    asm volatile("ldmatrix.sync.aligned.m8n8.x4.shared.b16 {%0,%1,%2,%3}, [%4];"
                 : "=r"(r[0]), "=r"(r[1]), "=r"(r[2]), "=r"(r[3]) : "r"(addr));
}
DEV_INLINE void mma_f16(float* c, const uint32_t* a, const uint32_t* b) {
    asm volatile(
        "mma.sync.aligned.m16n8k16.row.col.f32.f16.f16.f32 "
        "{%0,%1,%2,%3}, {%4,%5,%6,%7}, {%8,%9}, {%0,%1,%2,%3};"
        : "+f"(c[0]), "+f"(c[1]), "+f"(c[2]), "+f"(c[3])
        : "r"(a[0]), "r"(a[1]), "r"(a[2]), "r"(a[3]), "r"(b[0]), "r"(b[1]));
}
DEV_INLINE void cp_async16(uint32_t dst, const void* src) {
    asm volatile("cp.async.cg.shared.global [%0], [%1], 16;"
                 :: "r"(dst), "l"(__cvta_generic_to_global(src)) : "memory");
}
#define CP_COMMIT() asm volatile("cp.async.commit_group;" ::: "memory")
#define CP_WAIT0()  asm volatile("cp.async.wait_group 0;" ::: "memory")

DEV_INLINE void sts_half8(char* dst, float4 v) {
    __half2 h0 = __floats2half2_rn(v.x, v.y);
    __half2 h1 = __floats2half2_rn(v.z, v.w);
    uint2 u;
    u.x = *reinterpret_cast<uint32_t*>(&h0);
    u.y = *reinterpret_cast<uint32_t*>(&h1);
    *reinterpret_cast<uint2*>(dst) = u;
}

// ---------------- prepass: transpose + scale + fp16, near DRAM floor ----------------
// Block = (128 d) x (32 m) for one h. float4 coalesced reads, half2 writes.
__global__ __launch_bounds__(256)
void transpose_kernel(const float* __restrict__ w1a, const float* __restrict__ Ta) {
    __shared__ float tile[32][129];
    const int h  = blockIdx.y;           // 0..127
    const int d0 = blockIdx.x * 128;     // 16 blocks
    const float s = 1.0f / __ldg(Ta);
    #pragma unroll
    for (int p = 0; p < 4; p++) {
        const int idx = p * 256 + threadIdx.x;   // 0..1023
        const int m = idx >> 5, c = idx & 31;
        const float4 v = __ldg(reinterpret_cast<const float4*>(
            w1a + ((size_t)(m * kH2 + h)) * kD + d0) + c);
        tile[m][c * 4 + 0] = v.x; tile[m][c * 4 + 1] = v.y;
        tile[m][c * 4 + 2] = v.z; tile[m][c * 4 + 3] = v.w;
    }
    __syncthreads();
    #pragma unroll
    for (int p = 0; p < 8; p++) {
        const int idx = p * 256 + threadIdx.x;   // 0..2047
        const int dl = idx >> 4, mp = idx & 15;
        const __half2 hv = __floats2half2_rn(tile[2 * mp][dl] * s,
                                             tile[2 * mp + 1][dl] * s);
        *reinterpret_cast<__half2*>(
            &g_wt[((size_t)(d0 + dl) * kH2 + h) * kM + 2 * mp]) = hv;
    }
}

// ---------------- output transpose: g_outT[d][b] -> out[b][d] ----------------
__global__ __launch_bounds__(256)
void out_transpose_kernel(float* __restrict__ out) {
    __shared__ float tile[32][33];
    const int b0 = blockIdx.x * 32;      // 16 blocks
    const int d0 = blockIdx.y * 32;      // 64 blocks
    const int lane = threadIdx.x & 31;
    const int w    = threadIdx.x >> 5;
    #pragma unroll
    for (int i = w; i < 32; i += 8)
        tile[i][lane] = g_outT[(size_t)(d0 + i) * kB + b0 + lane];
    __syncthreads();
    #pragma unroll
    for (int i = w; i < 32; i += 8)
        out[(size_t)(b0 + i) * kD + d0 + lane] = tile[lane][i];
}

// ---------------- main kernel (R9 structure) ----------------
constexpr int PITCH_B   = 80;                 // bytes per fp16 row (ldsm-safe)
constexpr int ABYTES_H  = 128 * PITCH_B;      // 10240
constexpr int OFF_BH    = 2 * ABYTES_H;       // 20480
constexpr int OFF_PS    = OFF_BH + ABYTES_H;  // 30720
constexpr int OFF_W2    = OFF_PS + 2048;
constexpr int OFF_BI1   = OFF_W2 + 512;
constexpr int OFF_BI2   = OFF_BI1 + 512;
constexpr int SMEM_BYTES = OFF_BI2 + 32;

__global__ __launch_bounds__(256, 2)
void nlm_mma_kernel(const float* __restrict__ state,   // [B, D, M]
                    const float* __restrict__ b1a,     // [1, D, 2H]
                    const float* __restrict__ Ta,
                    const float* __restrict__ w1b,     // [H, 2, D]
                    const float* __restrict__ b1b,     // [1, D, 2]
                    const float* __restrict__ Tb) {
    extern __shared__ __align__(16) char sm[];
    char*   Ah   = sm;
    char*   Bh   = sm + OFF_BH;
    float*  ps   = reinterpret_cast<float*>(sm + OFF_PS);
    float2* sW2  = reinterpret_cast<float2*>(sm + OFF_W2);
    float*  sBi1 = reinterpret_cast<float*>(sm + OFF_BI1);
    float*  sBi2 = reinterpret_cast<float*>(sm + OFF_BI2);

    const int d    = blockIdx.x;
    const int tid  = threadIdx.x;
    const int lane = tid & 31;
    const int wid  = tid >> 5;
    const int mt   = wid & 3;      // m-tile: rows mt*32..+31
    const int nh   = wid >> 2;     // n-half: value cols nh*32..+31, gates +64

    const uint32_t sAh = smem_u32(Ah);
    const uint32_t sBh = smem_u32(Bh);

    const int arow = tid >> 3;     // coalesced staging: 1 wf per 128B line
    const int ac   = tid & 7;

    // ---- stage B via cp.async (raw fp16 copy; weights pre-scaled by 1/Ta) ----
    {
        const char* wsrc = reinterpret_cast<const char*>(g_wt + (size_t)d * kH2 * kM);
        #pragma unroll
        for (int t = 0; t < 2; t++) {
            const int c = tid + t * 256;
            const int h = c >> 2, cc = c & 3;
            cp_async16(sBh + (uint32_t)(h * PITCH_B + cc * 16), wsrc + h * 64 + cc * 16);
        }
        CP_COMMIT();
    }
    // ---- stage A(0): coalesced LDG.128 -> cvt -> STS.64 ----
    #pragma unroll
    for (int t = 0; t < 4; t++) {
        const int row = arow + t * 32;
        const float4 v = __ldg(reinterpret_cast<const float4*>(
            state + ((size_t)row * kD + d) * kM) + ac);
        sts_half8(Ah + row * PITCH_B + ac * 8, v);
    }
    const float rTa = 1.0f / __ldg(Ta);
    const float rTb = 1.0f / __ldg(Tb);
    if (tid < kH)
        sW2[tid] = make_float2(__ldg(w1b + (size_t)(tid * 2 + 0) * kD + d),
                               __ldg(w1b + (size_t)(tid * 2 + 1) * kD + d));
    if (tid < kH2) sBi1[tid] = b1a[(size_t)d * kH2 + tid] * rTa;  // pre-scaled bias
    if (tid < 2)   sBi2[tid] = b1b[(size_t)d * 2 + tid];

    // ---- ldmatrix addresses ----
    const uint32_t aBase = sAh +
        (uint32_t)((mt * 32 + ((lane >> 3) & 1) * 8 + (lane & 7)) * PITCH_B +
                   (lane >> 4) * 16);
    const uint32_t bBase = sBh +
        (uint32_t)((nh * 32 + ((lane >> 4) & 1) * 8 + (lane & 7)) * PITCH_B +
                   ((lane >> 3) & 1) * 16);
    const int hq = (lane & 3) * 2;

    CP_WAIT0();
    __syncthreads();

    // ---- B fragments: load ONCE (32 regs) ----
    uint32_t fbv[2][8], fbg[2][8];
    #pragma unroll
    for (int k = 0; k < 2; k++) {
        ldsm_x4(fbv[k] + 0, bBase + k * 32);
        ldsm_x4(fbv[k] + 4, bBase + 16 * PITCH_B + k * 32);
        ldsm_x4(fbg[k] + 0, bBase + 64 * PITCH_B + k * 32);
        ldsm_x4(fbg[k] + 4, bBase + 80 * PITCH_B + k * 32);
    }

    for (int g = 0; g < 4; g++) {
        // ---- prefetch A(g+1) phase 1 ----
        float4 pf0, pf1;
        if (g < 3) {
            const int b0n = (g + 1) * 128;
            pf0 = __ldg(reinterpret_cast<const float4*>(
                state + ((size_t)(b0n + arow) * kD + d) * kM) + ac);
            pf1 = __ldg(reinterpret_cast<const float4*>(
                state + ((size_t)(b0n + arow + 32) * kD + d) * kM) + ac);
        }
        // ---- finalize previous group's output (coalesced to g_outT) ----
        if (g > 0 && tid < 128) {
            const float4 pp = *reinterpret_cast<const float4*>(&ps[tid * 4]);
            const float u0 = (pp.x + pp.z + sBi2[0]) * rTb;
            const float u1 = (pp.y + pp.w + sBi2[1]) * rTb;
            g_outT[(size_t)d * kB + (g - 1) * 128 + tid] = u0 * fast_sigmoid(u1);
        }

        // ---- init accumulators with pre-scaled layer-1 biases ----
        float acc[2][8][4];
        #pragma unroll
        for (int q = 0; q < 4; q++) {
            const float2 bb = *reinterpret_cast<const float2*>(&sBi1[nh * 32 + q * 8 + hq]);
            const float2 bg = *reinterpret_cast<const float2*>(&sBi1[64 + nh * 32 + q * 8 + hq]);
            #pragma unroll
            for (int f = 0; f < 2; f++) {
                acc[f][q][0] = bb.x; acc[f][q][1] = bb.y;
                acc[f][q][2] = bb.x; acc[f][q][3] = bb.y;
                acc[f][q + 4][0] = bg.x; acc[f][q + 4][1] = bg.y;
                acc[f][q + 4][2] = bg.x; acc[f][q + 4][3] = bg.y;
            }
        }

        const uint32_t aA = aBase + (uint32_t)((g & 1) * ABYTES_H);
        char* nbuf = Ah + ((g + 1) & 1) * ABYTES_H;

        // ---- k = 0 ----
        {
            uint32_t a0[4], a1[4];
            ldsm_x4(a0, aA);
            ldsm_x4(a1, aA + 16 * PITCH_B);
            const uint32_t* bv = fbv[0];
            const uint32_t* bg = fbg[0];
            mma_f16(acc[0][0], a0, bv + 0); mma_f16(acc[0][1], a0, bv + 2);
            mma_f16(acc[0][2], a0, bv + 4); mma_f16(acc[0][3], a0, bv + 6);
            mma_f16(acc[0][4], a0, bg + 0); mma_f16(acc[0][5], a0, bg + 2);
            mma_f16(acc[0][6], a0, bg + 4); mma_f16(acc[0][7], a0, bg + 6);
            mma_f16(acc[1][0], a1, bv + 0); mma_f16(acc[1][1], a1, bv + 2);
            mma_f16(acc[1][2], a1, bv + 4); mma_f16(acc[1][3], a1, bv + 6);
            mma_f16(acc[1][4], a1, bg + 0); mma_f16(acc[1][5], a1, bg + 2);
            mma_f16(acc[1][6], a1, bg + 4); mma_f16(acc[1][7], a1, bg + 6);
        }
        // ---- store phase-1 prefetch, issue phase 2 ----
        if (g < 3) {
            sts_half8(nbuf + arow * PITCH_B + ac * 8, pf0);
            sts_half8(nbuf + (arow + 32) * PITCH_B + ac * 8, pf1);
            const int b0n = (g + 1) * 128;
            pf0 = __ldg(reinterpret_cast<const float4*>(
                state + ((size_t)(b0n + arow + 64) * kD + d) * kM) + ac);
            pf1 = __ldg(reinterpret_cast<const float4*>(
                state + ((size_t)(b0n + arow + 96) * kD + d) * kM) + ac);
        }
        // ---- k = 1 ----
        {
            uint32_t a0[4], a1[4];
            ldsm_x4(a0, aA + 32);
            ldsm_x4(a1, aA + 16 * PITCH_B + 32);
            const uint32_t* bv = fbv[1];
            const uint32_t* bg = fbg[1];
            mma_f16(acc[0][0], a0, bv + 0); mma_f16(acc[0][1], a0, bv + 2);
            mma_f16(acc[0][2], a0, bv + 4); mma_f16(acc[0][3], a0, bv + 6);
            mma_f16(acc[0][4], a0, bg + 0); mma_f16(acc[0][5], a0, bg + 2);
            mma_f16(acc[0][6], a0, bg + 4); mma_f16(acc[0][7], a0, bg + 6);
            mma_f16(acc[1][0], a1, bv + 0); mma_f16(acc[1][1], a1, bv + 2);
            mma_f16(acc[1][2], a1, bv + 4); mma_f16(acc[1][3], a1, bv + 6);
            mma_f16(acc[1][4], a1, bg + 0); mma_f16(acc[1][5], a1, bg + 2);
            mma_f16(acc[1][6], a1, bg + 4); mma_f16(acc[1][7], a1, bg + 6);
        }

        // ---- GLU1 + layer-2 partials (1/Ta already folded in), quad reduce -> ps ----
        float4 w2q[4];
        #pragma unroll
        for (int q = 0; q < 4; q++)
            w2q[q] = *reinterpret_cast<const float4*>(&sW2[nh * 32 + q * 8 + hq]);

        #pragma unroll
        for (int f = 0; f < 2; f++) {
            #pragma unroll
            for (int rh = 0; rh < 2; rh++) {
                float p0 = 0.0f, p1 = 0.0f;
                #pragma unroll
                for (int q = 0; q < 4; q++) {
                    const float x0 = acc[f][q][rh * 2 + 0] *
                                     fast_sigmoid(acc[f][q + 4][rh * 2 + 0]);
                    const float x1 = acc[f][q][rh * 2 + 1] *
                                     fast_sigmoid(acc[f][q + 4][rh * 2 + 1]);
                    p0 = fmaf(x0, w2q[q].x, p0); p1 = fmaf(x0, w2q[q].y, p1);
                    p0 = fmaf(x1, w2q[q].z, p0); p1 = fmaf(x1, w2q[q].w, p1);
                }
                p0 += __shfl_xor_sync(0xffffffffu, p0, 1);
                p0 += __shfl_xor_sync(0xffffffffu, p0, 2);
                p1 += __shfl_xor_sync(0xffffffffu, p1, 1);
                p1 += __shfl_xor_sync(0xffffffffu, p1, 2);
                if ((lane & 3) == 0) {
                    const int row = mt * 32 + f * 16 + rh * 8 + (lane >> 2);
                    *reinterpret_cast<float2*>(&ps[row * 4 + nh * 2]) = make_float2(p0, p1);
                }
            }
        }

        // ---- store phase-2 prefetch ----
        if (g < 3) {
            sts_half8(nbuf + (arow + 64) * PITCH_B + ac * 8, pf0);
            sts_half8(nbuf + (arow + 96) * PITCH_B + ac * 8, pf1);
        }
        __syncthreads();
    }

    // ---- finalize last group ----
    if (tid < 128) {
        const float4 pp = *reinterpret_cast<const float4*>(&ps[tid * 4]);
        const float u0 = (pp.x + pp.z + sBi2[0]) * rTb;
        const float u1 = (pp.y + pp.w + sBi2[1]) * rTb;
        g_outT[(size_t)d * kB + 3 * 128 + tid] = u0 * fast_sigmoid(u1);
    }
}

// ---------------- launch ----------------
extern "C" void kernel_launch(void* const* d_in, const int* in_sizes, int n_in,
                              void* d_out, int out_size) {
    const float* state = (const float*)d_in[0];
    const float* w1a   = (const float*)d_in[1];
    const float* b1a   = (const float*)d_in[2];
    const float* Ta    = (const float*)d_in[3];
    const float* w1b   = (const float*)d_in[4];
    const float* b1b   = (const float*)d_in[5];
    const float* Tb    = (const float*)d_in[6];
    float* out = (float*)d_out;

    cudaFuncSetAttribute(nlm_mma_kernel,
                         cudaFuncAttributeMaxDynamicSharedMemorySize, SMEM_BYTES);

    transpose_kernel<<<dim3(kD / 128, kH2), 256>>>(w1a, Ta);
    nlm_mma_kernel<<<kD, 256, SMEM_BYTES>>>(state, b1a, Ta, w1b, b1b, Tb);
    out_transpose_kernel<<<dim3(kB / 32, kD / 32), 256>>>(out);
}

// round 13
// speedup vs baseline: 1.2291x; 1.1650x over previous
#include <cuda_runtime.h>
#include <cuda_fp16.h>
#include <cstdint>

// NLM_7962869366897 — Round 13: barrier-free mainloop.
// R12 proved the strided output store was latency-hidden (g_outT detour lost
// time) and the main kernel is latency-bound with no saturated pipe. The
// untouched serializer is the per-group __syncthreads() convoy (5/CTA). Fix:
// stage ALL 512 A-rows into SMEM once (40KB fp16), give each group its own ps
// slice, and run all 4 groups' MMA+epilogue with ZERO intervening barriers.
// 2 syncs total. Mainloop math identical to R9 (m32n64, fp32 acc, B-resident).

#define DEV_INLINE __device__ __forceinline__

constexpr int kD  = 2048;
constexpr int kM  = 32;
constexpr int kH2 = 128;
constexpr int kH  = 64;
constexpr int kB  = 512;

__device__ __half g_wt[(size_t)kD * kH2 * kM];   // [d][h][m], fp16, pre-scaled by 1/Ta

DEV_INLINE float fast_sigmoid(float x) {
    float t; asm("tanh.approx.f32 %0, %1;" : "=f"(t) : "f"(0.5f * x));
    return fmaf(0.5f, t, 0.5f);
}
DEV_INLINE uint32_t smem_u32(const void* p) {
    uint32_t a;
    asm("{ .reg .u64 t; cvta.to.shared.u64 t, %1; cvt.u32.u64 %0, t; }" : "=r"(a) : "l"(p));
    return a;
}
DEV_INLINE void ldsm_x4(uint32_t* r, uint32_t addr) {
    asm volatile("ldmatrix.sync.aligned.m8n8.x4.shared.b16 {%0,%1,%2,%3}, [%4];"
                 : "=r"(r[0]), "=r"(r[1]), "=r"(r[2]), "=r"(r[3]) : "r"(addr));
}
DEV_INLINE void mma_f16(float* c, const uint32_t* a, const uint32_t* b) {
    asm volatile(
        "mma.sync.aligned.m16n8k16.row.col.f32.f16.f16.f32 "
        "{%0,%1,%2,%3}, {%4,%5,%6,%7}, {%8,%9}, {%0,%1,%2,%3};"
        : "+f"(c[0]), "+f"(c[1]), "+f"(c[2]), "+f"(c[3])
        : "r"(a[0]), "r"(a[1]), "r"(a[2]), "r"(a[3]), "r"(b[0]), "r"(b[1]));
}
DEV_INLINE void cp_async16(uint32_t dst, const void* src) {
    asm volatile("cp.async.cg.shared.global [%0], [%1], 16;"
                 :: "r"(dst), "l"(__cvta_generic_to_global(src)) : "memory");
}
#define CP_COMMIT() asm volatile("cp.async.commit_group;" ::: "memory")
#define CP_WAIT0()  asm volatile("cp.async.wait_group 0;" ::: "memory")

DEV_INLINE void sts_half8(char* dst, float4 v) {
    __half2 h0 = __floats2half2_rn(v.x, v.y);
    __half2 h1 = __floats2half2_rn(v.z, v.w);
    uint2 u;
    u.x = *reinterpret_cast<uint32_t*>(&h0);
    u.y = *reinterpret_cast<uint32_t*>(&h1);
    *reinterpret_cast<uint2*>(dst) = u;
}

// ---------------- prepass: transpose + scale(1/Ta) + fp16 ----------------
__global__ __launch_bounds__(256)
void transpose_kernel(const float* __restrict__ w1a, const float* __restrict__ Ta) {
    __shared__ float tile[32][129];
    const int h  = blockIdx.y;
    const int d0 = blockIdx.x * 128;
    const float s = 1.0f / __ldg(Ta);
    #pragma unroll
    for (int p = 0; p < 4; p++) {
        const int idx = p * 256 + threadIdx.x;
        const int m = idx >> 5, c = idx & 31;
        const float4 v = __ldg(reinterpret_cast<const float4*>(
            w1a + ((size_t)(m * kH2 + h)) * kD + d0) + c);
        tile[m][c * 4 + 0] = v.x; tile[m][c * 4 + 1] = v.y;
        tile[m][c * 4 + 2] = v.z; tile[m][c * 4 + 3] = v.w;
    }
    __syncthreads();
    #pragma unroll
    for (int p = 0; p < 8; p++) {
        const int idx = p * 256 + threadIdx.x;
        const int dl = idx >> 4, mp = idx & 15;
        const __half2 hv = __floats2half2_rn(tile[2 * mp][dl] * s,
                                             tile[2 * mp + 1][dl] * s);
        *reinterpret_cast<__half2*>(
            &g_wt[((size_t)(d0 + dl) * kH2 + h) * kM + 2 * mp]) = hv;
    }
}

// ---------------- main kernel ----------------
constexpr int PITCH_B = 80;                      // bytes per fp16 row (ldsm-safe)
constexpr int OFF_A   = 0;                       // 512 rows * 80 B = 40960
constexpr int OFF_BH  = 512 * PITCH_B;           // 40960
constexpr int OFF_PS  = OFF_BH + 128 * PITCH_B;  // 51200 (ps: 4 slices * 128 * 4 floats)
constexpr int OFF_W2  = OFF_PS + 8192;           // 59392
constexpr int OFF_BI1 = OFF_W2 + 512;            // 59904
constexpr int OFF_BI2 = OFF_BI1 + 512;           // 60416
constexpr int SMEM_BYTES = OFF_BI2 + 32;         // 60448 (x2 CTAs = 118 KB/SM)

__global__ __launch_bounds__(256, 2)
void nlm_mma_kernel(const float* __restrict__ state,   // [B, D, M]
                    const float* __restrict__ b1a,     // [1, D, 2H]
                    const float* __restrict__ Ta,
                    const float* __restrict__ w1b,     // [H, 2, D]
                    const float* __restrict__ b1b,     // [1, D, 2]
                    const float* __restrict__ Tb,
                    float* __restrict__ out) {         // [B, D]
    extern __shared__ __align__(16) char sm[];
    char*   Ah   = sm + OFF_A;
    float*  ps   = reinterpret_cast<float*>(sm + OFF_PS);
    float2* sW2  = reinterpret_cast<float2*>(sm + OFF_W2);
    float*  sBi1 = reinterpret_cast<float*>(sm + OFF_BI1);
    float*  sBi2 = reinterpret_cast<float*>(sm + OFF_BI2);

    const int d    = blockIdx.x;
    const int tid  = threadIdx.x;
    const int lane = tid & 31;
    const int wid  = tid >> 5;
    const int mt   = wid & 3;      // m-tile: rows mt*32..+31 within a 128-row group
    const int nh   = wid >> 2;     // n-half: value cols nh*32..+31, gates +64

    const uint32_t sAh = smem_u32(sm + OFF_A);
    const uint32_t sBh = smem_u32(sm + OFF_BH);

    const int arow = tid >> 3;     // coalesced staging: 1 wf per 128B line
    const int ac   = tid & 7;

    // ---- stage B via cp.async (weights pre-scaled by 1/Ta) ----
    {
        const char* wsrc = reinterpret_cast<const char*>(g_wt + (size_t)d * kH2 * kM);
        #pragma unroll
        for (int t = 0; t < 2; t++) {
            const int c = tid + t * 256;
            const int h = c >> 2, cc = c & 3;
            cp_async16(sBh + (uint32_t)(h * PITCH_B + cc * 16), wsrc + h * 64 + cc * 16);
        }
        CP_COMMIT();
    }
    // ---- stage ALL 512 A rows: phased LDG.128 -> cvt -> STS.64 ----
    #pragma unroll
    for (int ph = 0; ph < 4; ph++) {
        float4 v[4];
        #pragma unroll
        for (int j = 0; j < 4; j++) {
            const int row = arow + (ph * 4 + j) * 32;
            v[j] = __ldg(reinterpret_cast<const float4*>(
                state + ((size_t)row * kD + d) * kM) + ac);
        }
        #pragma unroll
        for (int j = 0; j < 4; j++) {
            const int row = arow + (ph * 4 + j) * 32;
            sts_half8(Ah + row * PITCH_B + ac * 8, v[j]);
        }
    }
    const float rTa = 1.0f / __ldg(Ta);
    const float rTb = 1.0f / __ldg(Tb);
    if (tid < kH)
        sW2[tid] = make_float2(__ldg(w1b + (size_t)(tid * 2 + 0) * kD + d),
                               __ldg(w1b + (size_t)(tid * 2 + 1) * kD + d));
    if (tid < kH2) sBi1[tid] = b1a[(size_t)d * kH2 + tid] * rTa;  // pre-scaled
    if (tid < 2)   sBi2[tid] = b1b[(size_t)d * 2 + tid];

    // ---- ldmatrix addresses ----
    const uint32_t aBase = sAh +
        (uint32_t)((mt * 32 + ((lane >> 3) & 1) * 8 + (lane & 7)) * PITCH_B +
                   (lane >> 4) * 16);
    const uint32_t bBase = sBh +
        (uint32_t)((nh * 32 + ((lane >> 4) & 1) * 8 + (lane & 7)) * PITCH_B +
                   ((lane >> 3) & 1) * 16);
    const int hq = (lane & 3) * 2;

    CP_WAIT0();
    __syncthreads();          // sync #1: A + B staged

    // ---- B fragments: load ONCE (32 regs) ----
    uint32_t fbv[2][8], fbg[2][8];
    #pragma unroll
    for (int k = 0; k < 2; k++) {
        ldsm_x4(fbv[k] + 0, bBase + k * 32);
        ldsm_x4(fbv[k] + 4, bBase + 16 * PITCH_B + k * 32);
        ldsm_x4(fbg[k] + 0, bBase + 64 * PITCH_B + k * 32);
        ldsm_x4(fbg[k] + 4, bBase + 80 * PITCH_B + k * 32);
    }

    // layer-2 weights + biases per thread (hoisted; uniform reads)
    float4 w2q[4];
    #pragma unroll
    for (int q = 0; q < 4; q++)
        w2q[q] = *reinterpret_cast<const float4*>(&sW2[nh * 32 + q * 8 + hq]);

    // ---- 4 groups, NO barriers in between ----
    #pragma unroll
    for (int g = 0; g < 4; g++) {
        float acc[2][8][4];
        #pragma unroll
        for (int q = 0; q < 4; q++) {
            const float2 bb = *reinterpret_cast<const float2*>(&sBi1[nh * 32 + q * 8 + hq]);
            const float2 bg = *reinterpret_cast<const float2*>(&sBi1[64 + nh * 32 + q * 8 + hq]);
            #pragma unroll
            for (int f = 0; f < 2; f++) {
                acc[f][q][0] = bb.x; acc[f][q][1] = bb.y;
                acc[f][q][2] = bb.x; acc[f][q][3] = bb.y;
                acc[f][q + 4][0] = bg.x; acc[f][q + 4][1] = bg.y;
                acc[f][q + 4][2] = bg.x; acc[f][q + 4][3] = bg.y;
            }
        }

        const uint32_t aA = aBase + (uint32_t)(g * 128 * PITCH_B);
        #pragma unroll
        for (int k = 0; k < 2; k++) {
            uint32_t a0[4], a1[4];
            ldsm_x4(a0, aA + k * 32);
            ldsm_x4(a1, aA + 16 * PITCH_B + k * 32);
            const uint32_t* bv = fbv[k];
            const uint32_t* bg = fbg[k];
            mma_f16(acc[0][0], a0, bv + 0); mma_f16(acc[0][1], a0, bv + 2);
            mma_f16(acc[0][2], a0, bv + 4); mma_f16(acc[0][3], a0, bv + 6);
            mma_f16(acc[0][4], a0, bg + 0); mma_f16(acc[0][5], a0, bg + 2);
            mma_f16(acc[0][6], a0, bg + 4); mma_f16(acc[0][7], a0, bg + 6);
            mma_f16(acc[1][0], a1, bv + 0); mma_f16(acc[1][1], a1, bv + 2);
            mma_f16(acc[1][2], a1, bv + 4); mma_f16(acc[1][3], a1, bv + 6);
            mma_f16(acc[1][4], a1, bg + 0); mma_f16(acc[1][5], a1, bg + 2);
            mma_f16(acc[1][6], a1, bg + 4); mma_f16(acc[1][7], a1, bg + 6);
        }

        // ---- GLU1 + layer-2 partials (1/Ta folded), quad reduce -> ps[g] ----
        #pragma unroll
        for (int f = 0; f < 2; f++) {
            #pragma unroll
            for (int rh = 0; rh < 2; rh++) {
                float p0 = 0.0f, p1 = 0.0f;
                #pragma unroll
                for (int q = 0; q < 4; q++) {
                    const float x0 = acc[f][q][rh * 2 + 0] *
                                     fast_sigmoid(acc[f][q + 4][rh * 2 + 0]);
                    const float x1 = acc[f][q][rh * 2 + 1] *
                                     fast_sigmoid(acc[f][q + 4][rh * 2 + 1]);
                    p0 = fmaf(x0, w2q[q].x, p0); p1 = fmaf(x0, w2q[q].y, p1);
                    p0 = fmaf(x1, w2q[q].z, p0); p1 = fmaf(x1, w2q[q].w, p1);
                }
                p0 += __shfl_xor_sync(0xffffffffu, p0, 1);
                p0 += __shfl_xor_sync(0xffffffffu, p0, 2);
                p1 += __shfl_xor_sync(0xffffffffu, p1, 1);
                p1 += __shfl_xor_sync(0xffffffffu, p1, 2);
                if ((lane & 3) == 0) {
                    const int row = g * 128 + mt * 32 + f * 16 + rh * 8 + (lane >> 2);
                    *reinterpret_cast<float2*>(&ps[row * 4 + nh * 2]) =
                        make_float2(p0, p1);
                }
            }
        }
    }

    __syncthreads();          // sync #2: all ps slices complete

    // ---- finalize: 2 outputs per thread, direct strided store ----
    #pragma unroll
    for (int p = 0; p < 2; p++) {
        const int row = tid + p * 256;
        const float4 pp = *reinterpret_cast<const float4*>(&ps[row * 4]);
        const float u0 = (pp.x + pp.z + sBi2[0]) * rTb;
        const float u1 = (pp.y + pp.w + sBi2[1]) * rTb;
        out[(size_t)row * kD + d] = u0 * fast_sigmoid(u1);
    }
}

// ---------------- launch ----------------
extern "C" void kernel_launch(void* const* d_in, const int* in_sizes, int n_in,
                              void* d_out, int out_size) {
    const float* state = (const float*)d_in[0];
    const float* w1a   = (const float*)d_in[1];
    const float* b1a   = (const float*)d_in[2];
    const float* Ta    = (const float*)d_in[3];
    const float* w1b   = (const float*)d_in[4];
    const float* b1b   = (const float*)d_in[5];
    const float* Tb    = (const float*)d_in[6];
    float* out = (float*)d_out;

    cudaFuncSetAttribute(nlm_mma_kernel,
                         cudaFuncAttributeMaxDynamicSharedMemorySize, SMEM_BYTES);

    transpose_kernel<<<dim3(kD / 128, kH2), 256>>>(w1a, Ta);
    nlm_mma_kernel<<<kD, 256, SMEM_BYTES>>>(state, b1a, Ta, w1b, b1b, Tb, out);
}